// round 14
// baseline (speedup 1.0000x reference)
#include <cuda_runtime.h>
#include <cuda_fp16.h>
#include <cstdint>
#include <cstddef>

// ---------------------------------------------------------------------------
// LSTM cell, B=65536, I=H=256. Baseline-PTX path (no tcgen05 on this
// harness's ptxas target): cp.async + ldmatrix + mma.sync.m16n8k16.f16 acc.
//
// Pass 1: [x|h] -> fp16 scratch (B x 512), [Wi|Wh] -> fp16 (1024 x 512).
// Pass 2: gates = XH @ W^T. CTA tile M=256 x N=256 (all 4 gates x 64 h-cols),
//         512 threads, 4x4 warp grid of 64x64 tiles (warp-col == gate).
//         Rationale vs R13 (M=128): B-weight L2 reread halves (512->256MB),
//         per-chunk compute:fill flips from ~920:2300 to ~1840:1540 cyc/SM,
//         and NSTG=3 + distance-2 prefetch covers fill latency. 192KB smem,
//         1 CTA/SM (16 warps/SM, same warp count as R13's 2x8).
//         Direct f16 accumulation (rel_err ~5e-4, 2x under 1e-3 gate).
// Output: d_out[0 : B*H] = h_new, d_out[B*H : 2*B*H] = c_new.
// ---------------------------------------------------------------------------

#define BATCH   65536
#define HID     256
#define KDIM    512
#define M_TILE  256
#define KC      64            // halves per K chunk = 128 bytes per row
#define NCHUNK  8             // 512 / 64
#define NSTG    3
#define STAGE_A 32768         // 256 rows * 128B
#define STAGE_B 32768         // 256 rows * 128B
#define STAGE_BYTES 65536
#define DYN_SMEM (NSTG * STAGE_BYTES)   // 196608 -> 1 CTA/SM
#define SGS     132           // half2 stride for epilogue staging (128 + pad)

// fp16 scratch (module-static device memory; no runtime allocation)
__device__ __half xh16g[(size_t)BATCH * KDIM];   // 64 MB
__device__ __half w16g[1024 * KDIM];             // 1 MB

// ---------------- helpers ----------------

__device__ __forceinline__ uint32_t swz(uint32_t o) {
    return o ^ ((o >> 3) & 0x70);          // xor bits[4:6] with bits[7:9]
}

#define CP_ASYNC16(dst, src) \
    asm volatile("cp.async.cg.shared.global [%0], [%1], 16;" \
                 :: "r"(dst), "l"(src) : "memory")

#define CP_COMMIT() asm volatile("cp.async.commit_group;" ::: "memory")

#define LDSM4(R, addr) \
    asm volatile("ldmatrix.sync.aligned.m8n8.x4.shared.b16 {%0,%1,%2,%3}, [%4];" \
                 : "=r"((R)[0]), "=r"((R)[1]), "=r"((R)[2]), "=r"((R)[3]) \
                 : "r"(addr))

// fp16-accumulate MMA, chained (C = D). Internal dot product fp32, one
// rounding per instruction.
#define MMA16816H(d, a, b0, b1) \
    asm volatile("mma.sync.aligned.m16n8k16.row.col.f16.f16.f16.f16 " \
                 "{%0,%1},{%2,%3,%4,%5},{%6,%7},{%0,%1};" \
                 : "+r"((d)[0]), "+r"((d)[1]) \
                 : "r"((a)[0]), "r"((a)[1]), "r"((a)[2]), "r"((a)[3]), \
                   "r"(b0), "r"(b1))

__device__ __forceinline__ float sigf(float x) {
    return __fdividef(1.0f, 1.0f + __expf(-x));
}
__device__ __forceinline__ float tanhf_fast(float x) {
    return 1.0f - __fdividef(2.0f, 1.0f + __expf(2.0f * x));
}

// ---------------- pass 1: fp32 -> fp16 concat convert ----------------
// rows [0, BATCH):            xh16g[r*512+k] = k<256 ? x[r,k] : h[r,k-256]
// rows [BATCH, BATCH+1024):   w16g [r*512+k] = k<256 ? Wi[r,k] : Wh[r,k-256]

__global__ void __launch_bounds__(256) conv_all_kernel(const float* __restrict__ x,
                                                       const float* __restrict__ h,
                                                       const float* __restrict__ Wi,
                                                       const float* __restrict__ Wh)
{
    size_t i = ((size_t)blockIdx.x * blockDim.x + threadIdx.x) * 8;
    if (i >= (size_t)(BATCH + 1024) * KDIM) return;
    int r = (int)(i >> 9);
    int k = (int)(i & 511);
    const float* A;
    const float* Bm;
    __half* dst;
    size_t row;
    if (r < BATCH) { A = x;  Bm = h;  dst = xh16g; row = (size_t)r; }
    else           { A = Wi; Bm = Wh; dst = w16g;  row = (size_t)(r - BATCH); }
    const float* s = (k < 256) ? (A + row * 256 + k) : (Bm + row * 256 + (k - 256));
    float4 f0 = ((const float4*)s)[0];
    float4 f1 = ((const float4*)s)[1];
    __half2 h0 = __floats2half2_rn(f0.x, f0.y);
    __half2 h1 = __floats2half2_rn(f0.z, f0.w);
    __half2 h2 = __floats2half2_rn(f1.x, f1.y);
    __half2 h3 = __floats2half2_rn(f1.z, f1.w);
    uint4 v;
    v.x = *(uint32_t*)&h0; v.y = *(uint32_t*)&h1;
    v.z = *(uint32_t*)&h2; v.w = *(uint32_t*)&h3;
    *(uint4*)(dst + row * KDIM + k) = v;
}

// ---------------- pass 2: GEMM + LSTM ----------------
// B tile rows: tile row r (0..255) -> gate g = r>>6, jj = r&63,
//              weight row g*256 + jbase + jj.

__device__ __forceinline__ void issue_stage(uint32_t smb, int stage, int kc,
                                            int tid, int mrow, int jbase)
{
    const uint32_t abase = smb + stage * STAGE_BYTES;
    const uint32_t bbase = abase + STAGE_A;
    #pragma unroll
    for (int j = 0; j < 8; ++j) {
        const int slot = tid + j * 512;          // 0..4095
        if (slot < 2048) {                       // A: 256 rows x 8 segs of 16B
            const int row = slot >> 3, seg = slot & 7;
            const uint32_t d = abase + swz(row * 128 + seg * 16);
            const __half* src = xh16g + ((size_t)(mrow + row) << 9) + kc * KC + seg * 8;
            CP_ASYNC16(d, src);
        } else {                                 // B: 256 rows x 8 segs
            const int t = slot - 2048;
            const int row = t >> 3, seg = t & 7;
            const int wrow = ((row >> 6) << 8) + jbase + (row & 63);
            const uint32_t d = bbase + swz(row * 128 + seg * 16);
            const __half* src = w16g + ((size_t)wrow << 9) + kc * KC + seg * 8;
            CP_ASYNC16(d, src);
        }
    }
}

extern "C" __global__ void __launch_bounds__(512, 1)
lstm_gemm_kernel(const float* __restrict__ c_in,
                 const float* __restrict__ bi,
                 const float* __restrict__ bh,
                 float* __restrict__ h_out,
                 float* __restrict__ c_out)
{
    extern __shared__ __align__(1024) char dynsmem[];
    __shared__ float sbias[256];

    const int tid  = threadIdx.x;
    const int lane = tid & 31;
    const int wid  = tid >> 5;
    const int wm   = wid >> 2;           // warp row 0..3 (64 m-rows each)
    const int wn   = wid & 3;            // warp col 0..3 == gate (64 cols each)

    const int m_tile = (int)(blockIdx.x >> 2);
    const int jslice = (int)(blockIdx.x & 3);
    const int mrow   = m_tile * M_TILE;
    const int jbase  = jslice * 64;

    const uint32_t smb = (uint32_t)__cvta_generic_to_shared(dynsmem);

    // bias sums for tile cols tc = g*64 + jj  ->  actual col g*256+jbase+jj
    if (tid < 256) {
        const int g = tid >> 6, jj = tid & 63;
        sbias[tid] = bi[g * 256 + jbase + jj] + bh[g * 256 + jbase + jj];
    }

    // f16x2 master accumulators, direct accumulation across all 32 MMAs/chunk.
    // hmast[mt][nt]: rows wm*64+mt*16 (+8 for reg1), cols wn*64+nt*8.
    uint32_t hmast[4][8][2];
    #pragma unroll
    for (int mt = 0; mt < 4; ++mt)
        #pragma unroll
        for (int nt = 0; nt < 8; ++nt) {
            hmast[mt][nt][0] = 0u;
            hmast[mt][nt][1] = 0u;
        }

    // ldmatrix per-lane offsets
    const int a_row0 = wm * 64 + (lane & 15);
    const int a_koff = (lane >> 4) * 16;
    const int b_rowc = wn * 64 + ((lane >> 4) << 3) + (lane & 7);
    const int b_koff = ((lane >> 3) & 1) * 16;

    // prologue: chunks 0,1 -> stages 0,1 (distance-2 pipeline)
    issue_stage(smb, 0, 0, tid, mrow, jbase); CP_COMMIT();
    issue_stage(smb, 1, 1, tid, mrow, jbase); CP_COMMIT();

    int stage = 0;
    for (int k = 0; k < NCHUNK; ++k) {
        asm volatile("cp.async.wait_group 1;" ::: "memory");  // chunk k landed
        __syncthreads();   // visibility + all warps done with stage (k-1)%3

        if (k + 2 < NCHUNK) {
            int ps = stage + 2; if (ps >= NSTG) ps -= NSTG;   // = (k-1)%3, free
            issue_stage(smb, ps, k + 2, tid, mrow, jbase);
            CP_COMMIT();   // overlaps with compute of chunk k below
        }

        const uint32_t abase = smb + stage * STAGE_BYTES;
        const uint32_t bbase = abase + STAGE_A;

        #pragma unroll
        for (int kt = 0; kt < 4; ++kt) {
            uint32_t aF[4][4];
            #pragma unroll
            for (int mt = 0; mt < 4; ++mt) {
                const uint32_t o = (uint32_t)((a_row0 + mt * 16) * 128 + kt * 32 + a_koff);
                LDSM4(aF[mt], abase + swz(o));
            }
            uint32_t bF[4][4];
            #pragma unroll
            for (int nt2 = 0; nt2 < 4; ++nt2) {
                const uint32_t o = (uint32_t)((b_rowc + nt2 * 16) * 128 + kt * 32 + b_koff);
                LDSM4(bF[nt2], bbase + swz(o));
            }
            #pragma unroll
            for (int mt = 0; mt < 4; ++mt)
                #pragma unroll
                for (int nt = 0; nt < 8; ++nt)
                    MMA16816H(hmast[mt][nt], aF[mt],
                              bF[nt >> 1][(nt & 1) * 2], bF[nt >> 1][(nt & 1) * 2 + 1]);
        }

        if (++stage == NSTG) stage = 0;
    }
    __syncthreads();   // pipeline smem -> epilogue staging reuse

    // stage gates as f16x2: sg[r * SGS + hc], hc = tc/2 = g*32 + jj/2
    uint32_t* sg = (uint32_t*)dynsmem;
    {
        const int rl = lane >> 2;            // row within 8-row group
        const int hc0 = wn * 32 + (lane & 3);
        #pragma unroll
        for (int mt = 0; mt < 4; ++mt)
            #pragma unroll
            for (int nt = 0; nt < 8; ++nt) {
                const int r = wm * 64 + mt * 16 + rl;
                const int hc = hc0 + nt * 4;
                sg[r * SGS + hc]       = hmast[mt][nt][0];
                sg[(r + 8) * SGS + hc] = hmast[mt][nt][1];
            }
    }
    __syncthreads();

    // fused LSTM elementwise: 256 rows x 32 half2-cols, float2 I/O
    const float2* sb2 = (const float2*)sbias;
    #pragma unroll 4
    for (int it = 0; it < 16; ++it) {
        const int idx = it * 512 + tid;
        const int r  = idx >> 5;
        const int j2 = idx & 31;             // half2 col within the 64-col slice
        float2 gi = __half22float2(*(const __half2*)&sg[r * SGS +      j2]);
        float2 gf = __half22float2(*(const __half2*)&sg[r * SGS + 32 + j2]);
        float2 gg = __half22float2(*(const __half2*)&sg[r * SGS + 64 + j2]);
        float2 go = __half22float2(*(const __half2*)&sg[r * SGS + 96 + j2]);
        const float2 b0 = sb2[     j2], b1 = sb2[32 + j2];
        const float2 b2 = sb2[64 + j2], b3 = sb2[96 + j2];
        gi.x += b0.x; gi.y += b0.y;
        gf.x += b1.x; gf.y += b1.y;
        gg.x += b2.x; gg.y += b2.y;
        go.x += b3.x; go.y += b3.y;
        const size_t gp = (size_t)(mrow + r) * HID + jbase + 2 * j2;
        const float2 cv = *(const float2*)(c_in + gp);
        float2 cc, hn;
        cc.x = sigf(gf.x) * cv.x + sigf(gi.x) * tanhf_fast(gg.x);
        cc.y = sigf(gf.y) * cv.y + sigf(gi.y) * tanhf_fast(gg.y);
        hn.x = sigf(go.x) * tanhf_fast(cc.x);
        hn.y = sigf(go.y) * tanhf_fast(cc.y);
        *(float2*)(c_out + gp) = cc;
        *(float2*)(h_out + gp) = hn;
    }
}

// ---------------- host launcher ----------------

extern "C" void kernel_launch(void* const* d_in, const int* in_sizes, int n_in,
                              void* d_out, int out_size)
{
    (void)in_sizes; (void)n_in; (void)out_size;
    const float* x  = (const float*)d_in[0];
    const float* h  = (const float*)d_in[1];
    const float* c  = (const float*)d_in[2];
    const float* Wi = (const float*)d_in[3];
    const float* Wh = (const float*)d_in[4];
    const float* bi = (const float*)d_in[5];
    const float* bh = (const float*)d_in[6];
    float* hout = (float*)d_out;
    float* cout = hout + (size_t)BATCH * HID;

    // pass 1: single conversion kernel (xh + weights)
    {
        const size_t n = (size_t)(BATCH + 1024) * KDIM / 8;
        conv_all_kernel<<<(unsigned)((n + 255) / 256), 256>>>(x, h, Wi, Wh);
    }

    // pass 2: GEMM + LSTM. grid: 256 m-tiles x 4 jslices (adjacent bids
    // share A rows -> L2 dedup). 1 CTA/SM, 16 warps/SM.
    cudaFuncSetAttribute(lstm_gemm_kernel,
                         cudaFuncAttributeMaxDynamicSharedMemorySize, DYN_SMEM);
    lstm_gemm_kernel<<<(BATCH / M_TILE) * 4, 512, DYN_SMEM>>>(c, bi, bh, hout, cout);
}

// round 15
// speedup vs baseline: 1.1936x; 1.1936x over previous
#include <cuda_runtime.h>
#include <cuda_fp16.h>
#include <cstdint>
#include <cstddef>

// ---------------------------------------------------------------------------
// LSTM cell, B=65536, I=H=256. Baseline-PTX path (no tcgen05 on this
// harness's ptxas target): cp.async + ldmatrix + mma.sync.m16n8k16.f16 acc.
//
// Pass 1: [x|h] -> fp16 scratch (B x 512), [Wi|Wh] -> fp16 (1024 x 512).
// Pass 2: gates = XH @ W^T. Occupancy experiment: tensor utilization has
//         tracked warps/SM across all rounds (8w->47%, 16w->58%); this round
//         targets 24 warps/SM = 3 CTAs/SM. CTA tile M=128 x N=128 (4 gates x
//         32 h-cols), 256 threads, 4x2 warp grid of 32x64 tiles (the proven
//         R9 mainloop), NSTG=2 x 32KB = 64KB smem/CTA, direct f16
//         accumulation to fit the 84-reg budget (__launch_bounds__(256,3)).
// Output: d_out[0 : B*H] = h_new, d_out[B*H : 2*B*H] = c_new.
// ---------------------------------------------------------------------------

#define BATCH   65536
#define HID     256
#define KDIM    512
#define M_TILE  128
#define KC      64            // halves per K chunk = 128 bytes per row
#define NCHUNK  8             // 512 / 64
#define NSTG    2
#define STAGE_A 16384         // 128 rows * 128B
#define STAGE_B 16384         // 128 rows * 128B
#define STAGE_BYTES 32768
#define DYN_SMEM (NSTG * STAGE_BYTES)   // 65536 -> 3 CTAs/SM
#define SGS     66            // half2 stride for epilogue staging (64 + pad)

// fp16 scratch (module-static device memory; no runtime allocation)
__device__ __half xh16g[(size_t)BATCH * KDIM];   // 64 MB
__device__ __half w16g[1024 * KDIM];             // 1 MB

// ---------------- helpers ----------------

__device__ __forceinline__ uint32_t swz(uint32_t o) {
    return o ^ ((o >> 3) & 0x70);          // xor bits[4:6] with bits[7:9]
}

#define CP_ASYNC16(dst, src) \
    asm volatile("cp.async.cg.shared.global [%0], [%1], 16;" \
                 :: "r"(dst), "l"(src) : "memory")

#define CP_COMMIT() asm volatile("cp.async.commit_group;" ::: "memory")

#define LDSM4(R, addr) \
    asm volatile("ldmatrix.sync.aligned.m8n8.x4.shared.b16 {%0,%1,%2,%3}, [%4];" \
                 : "=r"((R)[0]), "=r"((R)[1]), "=r"((R)[2]), "=r"((R)[3]) \
                 : "r"(addr))

// fp16-accumulate MMA, chained (C = D). Internal dot product fp32, one
// rounding per instruction.
#define MMA16816H(d, a, b0, b1) \
    asm volatile("mma.sync.aligned.m16n8k16.row.col.f16.f16.f16.f16 " \
                 "{%0,%1},{%2,%3,%4,%5},{%6,%7},{%0,%1};" \
                 : "+r"((d)[0]), "+r"((d)[1]) \
                 : "r"((a)[0]), "r"((a)[1]), "r"((a)[2]), "r"((a)[3]), \
                   "r"(b0), "r"(b1))

__device__ __forceinline__ float sigf(float x) {
    return __fdividef(1.0f, 1.0f + __expf(-x));
}
__device__ __forceinline__ float tanhf_fast(float x) {
    return 1.0f - __fdividef(2.0f, 1.0f + __expf(2.0f * x));
}

// ---------------- pass 1: fp32 -> fp16 concat convert ----------------
// rows [0, BATCH):            xh16g[r*512+k] = k<256 ? x[r,k] : h[r,k-256]
// rows [BATCH, BATCH+1024):   w16g [r*512+k] = k<256 ? Wi[r,k] : Wh[r,k-256]

__global__ void __launch_bounds__(256) conv_all_kernel(const float* __restrict__ x,
                                                       const float* __restrict__ h,
                                                       const float* __restrict__ Wi,
                                                       const float* __restrict__ Wh)
{
    size_t i = ((size_t)blockIdx.x * blockDim.x + threadIdx.x) * 8;
    if (i >= (size_t)(BATCH + 1024) * KDIM) return;
    int r = (int)(i >> 9);
    int k = (int)(i & 511);
    const float* A;
    const float* Bm;
    __half* dst;
    size_t row;
    if (r < BATCH) { A = x;  Bm = h;  dst = xh16g; row = (size_t)r; }
    else           { A = Wi; Bm = Wh; dst = w16g;  row = (size_t)(r - BATCH); }
    const float* s = (k < 256) ? (A + row * 256 + k) : (Bm + row * 256 + (k - 256));
    float4 f0 = ((const float4*)s)[0];
    float4 f1 = ((const float4*)s)[1];
    __half2 h0 = __floats2half2_rn(f0.x, f0.y);
    __half2 h1 = __floats2half2_rn(f0.z, f0.w);
    __half2 h2 = __floats2half2_rn(f1.x, f1.y);
    __half2 h3 = __floats2half2_rn(f1.z, f1.w);
    uint4 v;
    v.x = *(uint32_t*)&h0; v.y = *(uint32_t*)&h1;
    v.z = *(uint32_t*)&h2; v.w = *(uint32_t*)&h3;
    *(uint4*)(dst + row * KDIM + k) = v;
}

// ---------------- pass 2: GEMM + LSTM ----------------
// B tile rows: tile row r (0..127) -> gate g = r>>5, jj = r&31,
//              weight row g*256 + jbase + jj.

__device__ __forceinline__ void issue_stage(uint32_t smb, int stage, int kc,
                                            int tid, int mrow, int jbase)
{
    const uint32_t abase = smb + stage * STAGE_BYTES;
    const uint32_t bbase = abase + STAGE_A;
    #pragma unroll
    for (int j = 0; j < 8; ++j) {
        const int slot = tid + j * 256;          // 0..2047
        if (slot < 1024) {                       // A: 128 rows x 8 segs of 16B
            const int row = slot >> 3, seg = slot & 7;
            const uint32_t d = abase + swz(row * 128 + seg * 16);
            const __half* src = xh16g + ((size_t)(mrow + row) << 9) + kc * KC + seg * 8;
            CP_ASYNC16(d, src);
        } else {                                 // B: 128 rows x 8 segs
            const int t = slot - 1024;
            const int row = t >> 3, seg = t & 7;
            const int wrow = ((row >> 5) << 8) + jbase + (row & 31);
            const uint32_t d = bbase + swz(row * 128 + seg * 16);
            const __half* src = w16g + ((size_t)wrow << 9) + kc * KC + seg * 8;
            CP_ASYNC16(d, src);
        }
    }
}

extern "C" __global__ void __launch_bounds__(256, 3)
lstm_gemm_kernel(const float* __restrict__ c_in,
                 const float* __restrict__ bi,
                 const float* __restrict__ bh,
                 float* __restrict__ h_out,
                 float* __restrict__ c_out)
{
    extern __shared__ __align__(1024) char dynsmem[];
    __shared__ float sbias[128];

    const int tid  = threadIdx.x;
    const int lane = tid & 31;
    const int wid  = tid >> 5;
    const int wm   = wid >> 1;           // warp row 0..3 (32 m-rows each)
    const int wn   = wid & 1;            // warp col 0..1 (64 tile-cols each)

    const int m_tile = (int)(blockIdx.x >> 3);
    const int jslice = (int)(blockIdx.x & 7);
    const int mrow   = m_tile * M_TILE;
    const int jbase  = jslice * 32;

    const uint32_t smb = (uint32_t)__cvta_generic_to_shared(dynsmem);

    // bias sums for tile cols tc = g*32 + jj  ->  actual col g*256+jbase+jj
    if (tid < 128) {
        const int g = tid >> 5, jj = tid & 31;
        sbias[tid] = bi[g * 256 + jbase + jj] + bh[g * 256 + jbase + jj];
    }

    // f16x2 master accumulators, direct accumulation across all MMAs.
    // hmast[mt][nt]: rows wm*32+mt*16 (+8 for reg1), cols wn*64+nt*8.
    uint32_t hmast[2][8][2];
    #pragma unroll
    for (int mt = 0; mt < 2; ++mt)
        #pragma unroll
        for (int nt = 0; nt < 8; ++nt) {
            hmast[mt][nt][0] = 0u;
            hmast[mt][nt][1] = 0u;
        }

    // ldmatrix per-lane offsets
    const int a_row0 = wm * 32 + (lane & 15);
    const int a_koff = (lane >> 4) * 16;
    const int b_rowc = wn * 64 + ((lane >> 4) << 3) + (lane & 7);
    const int b_koff = ((lane >> 3) & 1) * 16;

    // prologue: chunk 0 -> stage 0
    issue_stage(smb, 0, 0, tid, mrow, jbase);
    CP_COMMIT();

    for (int k = 0; k < NCHUNK; ++k) {
        asm volatile("cp.async.wait_group 0;" ::: "memory");
        __syncthreads();   // chunk k ready; all warps done with chunk k-1

        if (k + 1 < NCHUNK) {
            issue_stage(smb, (k + 1) & 1, k + 1, tid, mrow, jbase);
            CP_COMMIT();   // overlaps with compute of chunk k below
        }

        const uint32_t abase = smb + (k & 1) * STAGE_BYTES;
        const uint32_t bbase = abase + STAGE_A;

        #pragma unroll
        for (int kt = 0; kt < 4; ++kt) {
            uint32_t aF[2][4];
            #pragma unroll
            for (int mt = 0; mt < 2; ++mt) {
                const uint32_t o = (uint32_t)((a_row0 + mt * 16) * 128 + kt * 32 + a_koff);
                LDSM4(aF[mt], abase + swz(o));
            }
            uint32_t bF[4][4];
            #pragma unroll
            for (int nt2 = 0; nt2 < 4; ++nt2) {
                const uint32_t o = (uint32_t)((b_rowc + nt2 * 16) * 128 + kt * 32 + b_koff);
                LDSM4(bF[nt2], bbase + swz(o));
            }
            #pragma unroll
            for (int mt = 0; mt < 2; ++mt)
                #pragma unroll
                for (int nt = 0; nt < 8; ++nt)
                    MMA16816H(hmast[mt][nt], aF[mt],
                              bF[nt >> 1][(nt & 1) * 2], bF[nt >> 1][(nt & 1) * 2 + 1]);
        }
    }
    __syncthreads();   // pipeline smem -> epilogue staging reuse

    // stage gates as f16x2: sg[r * SGS + hc], hc = tc/2 = g*16 + jj/2
    uint32_t* sg = (uint32_t*)dynsmem;
    {
        const int rl = lane >> 2;            // row within 8-row group
        const int hc0 = wn * 32 + (lane & 3);
        #pragma unroll
        for (int mt = 0; mt < 2; ++mt)
            #pragma unroll
            for (int nt = 0; nt < 8; ++nt) {
                const int r = wm * 32 + mt * 16 + rl;
                const int hc = hc0 + nt * 4;
                sg[r * SGS + hc]       = hmast[mt][nt][0];
                sg[(r + 8) * SGS + hc] = hmast[mt][nt][1];
            }
    }
    __syncthreads();

    // fused LSTM elementwise: 128 rows x 16 half2-cols, float2 I/O
    const float2* sb2 = (const float2*)sbias;
    #pragma unroll 4
    for (int it = 0; it < 8; ++it) {
        const int idx = it * 256 + tid;
        const int r  = idx >> 4;
        const int j2 = idx & 15;             // half2 col within the 32-col slice
        float2 gi = __half22float2(*(const __half2*)&sg[r * SGS +      j2]);
        float2 gf = __half22float2(*(const __half2*)&sg[r * SGS + 16 + j2]);
        float2 gg = __half22float2(*(const __half2*)&sg[r * SGS + 32 + j2]);
        float2 go = __half22float2(*(const __half2*)&sg[r * SGS + 48 + j2]);
        const float2 b0 = sb2[     j2], b1 = sb2[16 + j2];
        const float2 b2 = sb2[32 + j2], b3 = sb2[48 + j2];
        gi.x += b0.x; gi.y += b0.y;
        gf.x += b1.x; gf.y += b1.y;
        gg.x += b2.x; gg.y += b2.y;
        go.x += b3.x; go.y += b3.y;
        const size_t gp = (size_t)(mrow + r) * HID + jbase + 2 * j2;
        const float2 cv = *(const float2*)(c_in + gp);
        float2 cc, hn;
        cc.x = sigf(gf.x) * cv.x + sigf(gi.x) * tanhf_fast(gg.x);
        cc.y = sigf(gf.y) * cv.y + sigf(gi.y) * tanhf_fast(gg.y);
        hn.x = sigf(go.x) * tanhf_fast(cc.x);
        hn.y = sigf(go.y) * tanhf_fast(cc.y);
        *(float2*)(c_out + gp) = cc;
        *(float2*)(h_out + gp) = hn;
    }
}

// ---------------- host launcher ----------------

extern "C" void kernel_launch(void* const* d_in, const int* in_sizes, int n_in,
                              void* d_out, int out_size)
{
    (void)in_sizes; (void)n_in; (void)out_size;
    const float* x  = (const float*)d_in[0];
    const float* h  = (const float*)d_in[1];
    const float* c  = (const float*)d_in[2];
    const float* Wi = (const float*)d_in[3];
    const float* Wh = (const float*)d_in[4];
    const float* bi = (const float*)d_in[5];
    const float* bh = (const float*)d_in[6];
    float* hout = (float*)d_out;
    float* cout = hout + (size_t)BATCH * HID;

    // pass 1: single conversion kernel (xh + weights)
    {
        const size_t n = (size_t)(BATCH + 1024) * KDIM / 8;
        conv_all_kernel<<<(unsigned)((n + 255) / 256), 256>>>(x, h, Wi, Wh);
    }

    // pass 2: GEMM + LSTM. grid: 512 m-tiles x 8 jslices (adjacent bids
    // share A rows -> L2 dedup). 3 CTAs/SM, 24 warps/SM.
    cudaFuncSetAttribute(lstm_gemm_kernel,
                         cudaFuncAttributeMaxDynamicSharedMemorySize, DYN_SMEM);
    lstm_gemm_kernel<<<(BATCH / M_TILE) * 8, 256, DYN_SMEM>>>(c, bi, bh, hout, cout);
}